// round 12
// baseline (speedup 1.0000x reference)
#include <cuda_runtime.h>
#include <cuda_bf16.h>
#include <math.h>

#define NB 64
#define NT 512
#define NM 8
#define NV 50
#define TT  128          // timesteps per CTA tile
#define NTILE 4          // NT / TT
#define TPB 128
#define WPAD 56          // padded w (7 n-tiles of 8)
#define LUTN 1024
#define LUTF 1024.0f

typedef unsigned int u32;

__device__ float2 g_lut[NM][LUTN];

// ---------------- helpers ----------------
__device__ __forceinline__ u32 smem_u32(const void* p){
  u32 a; asm("{ .reg .u64 t; cvta.to.shared.u64 t, %1; cvt.u32.u64 %0, t; }" : "=r"(a) : "l"(p));
  return a;
}
__device__ __forceinline__ float ex2f(float x){ float r; asm("ex2.approx.f32 %0, %1;" : "=f"(r) : "f"(x)); return r; }
__device__ __forceinline__ float rcpf(float x){ float r; asm("rcp.approx.f32 %0, %1;" : "=f"(r) : "f"(x)); return r; }

__device__ __forceinline__ void mma_bf16(float* d, const u32* a, u32 b0, u32 b1){
  asm volatile("mma.sync.aligned.m16n8k16.row.col.f32.bf16.bf16.f32 "
    "{%0,%1,%2,%3}, {%4,%5,%6,%7}, {%8,%9}, {%0,%1,%2,%3};"
    : "+f"(d[0]), "+f"(d[1]), "+f"(d[2]), "+f"(d[3])
    : "r"(a[0]), "r"(a[1]), "r"(a[2]), "r"(a[3]), "r"(b0), "r"(b1));
}
// Non-transposed ldmatrix: smem rows = n, row elements = k (consecutive k packed) -> .col B frag.
__device__ __forceinline__ void ldsm2(u32 &r0, u32 &r1, u32 addr){
  asm volatile("ldmatrix.sync.aligned.m8n8.x2.shared.b16 {%0,%1}, [%2];"
    : "=r"(r0), "=r"(r1) : "r"(addr));
}

// split a pair of fp32 into packed bf16 hi and bf16 lo-residual (elem0 in low half)
__device__ __forceinline__ void split2(float f0, float f1, u32 &hp, u32 &lp){
  __nv_bfloat16 h0 = __float2bfloat16(f0), h1 = __float2bfloat16(f1);
  float l0 = f0 - __bfloat162float(h0);
  float l1 = f1 - __bfloat162float(h1);
  __nv_bfloat16 g0 = __float2bfloat16(l0), g1 = __float2bfloat16(l1);
  hp = ((u32)__bfloat16_as_ushort(h1) << 16) | (u32)__bfloat16_as_ushort(h0);
  lp = ((u32)__bfloat16_as_ushort(g1) << 16) | (u32)__bfloat16_as_ushort(g0);
}

// ---------------- LUT builder ----------------
__global__ void lut_build(const float* __restrict__ w1, const float* __restrict__ b1,
                          const float* __restrict__ w2, const float* __restrict__ b2)
{
  const int m = blockIdx.x;
  const float LOG2E = 1.4426950408889634f;
  float W1[8], B1[8], W2[8];
  float bias = b2[m];
  float M = bias, lim = bias;
  #pragma unroll
  for (int j = 0; j < 8; j++){
    W1[j] = w1[m*8+j]; B1[j] = b1[m*8+j]; W2[j] = w2[m*8+j];
    M += fabsf(W2[j]);
    lim += W2[j] * (W1[j] > 0.f ? 1.f : (W1[j] < 0.f ? -1.f : tanhf(B1[j])));
  }
  M *= LOG2E; lim *= LOG2E;

  for (int i = threadIdx.x; i < LUTN; i += blockDim.x){
    float f0, f1;
    {
      float u = (float)i / LUTF;
      float h = u / (1.f - u);
      float s = bias;
      #pragma unroll
      for (int j = 0; j < 8; j++) s += W2[j] * tanhf(fmaf(h, W1[j], B1[j]));
      f0 = s * LOG2E;
    }
    if (i + 1 == LUTN) f1 = lim;
    else {
      float u = (float)(i + 1) / LUTF;
      float h = u / (1.f - u);
      float s = bias;
      #pragma unroll
      for (int j = 0; j < 8; j++) s += W2[j] * tanhf(fmaf(h, W1[j], B1[j]));
      f1 = s * LOG2E;
    }
    g_lut[m][i] = make_float2(f0 - M, f1 - f0);
  }
}

// ---------------- main kernel ----------------
__device__ __forceinline__ void node_update(float gval, float A, float C,
                                            const float2* __restrict__ sLUT,
                                            float &l, float &acc)
{
  float h = fmaxf(fmaf(gval, A, C), 0.f);
  float r = rcpf(1.f + h);
  float q = fmaf(r, -LUTF, LUTF);
  int   i = (int)q;
  i = min(max(i, 0), LUTN - 1);
  float fr = q - (float)i;
  float2 e = sLUT[i];
  float p = ex2f(fmaf(fr, e.y, e.x));
  l += p;
  acc = fmaf(h, p, acc);
}

__global__ void __launch_bounds__(TPB)
ima_kernel(const float* __restrict__ x,  const float* __restrict__ PA,
           const float* __restrict__ conv_w, const float* __restrict__ conv_b,
           const float* __restrict__ bn_gamma, const float* __restrict__ bn_beta,
           const float* __restrict__ bn_mean,  const float* __restrict__ bn_var,
           float* __restrict__ out)
{
  // B = PA^T: smem rows = w (n dim), 64 v (k dim) bf16 = 128 B/row, XOR-swizzled 16B chunks
  __shared__ __align__(128) unsigned char p_hi[WPAD * 128];   // 7 KB
  __shared__ __align__(128) unsigned char p_lo[WPAD * 128];   // 7 KB
  __shared__ float2 sLUT[LUTN];                               // 8 KB  (total ~22.4 KB)

  const int tid  = threadIdx.x;
  const int wid  = tid >> 5;
  const int lane = tid & 31;
  const int gid  = lane >> 2;       // groupID 0..7
  const int tig  = lane & 3;        // threadID_in_group 0..3

  const int blk  = blockIdx.x;      // 0..2047
  const int tile = blk & (NTILE - 1);
  const int bm   = blk / NTILE;
  const int m    = bm & (NM - 1);
  const int b    = bm / NM;

  // ---- zero B tiles (backdrop for v>=50 / w>=50) ----
  for (int i = tid; i < (WPAD * 128) / 4; i += TPB){
    ((u32*)p_hi)[i] = 0u;
    ((u32*)p_lo)[i] = 0u;
  }
  for (int i = tid; i < LUTN; i += TPB) sLUT[i] = g_lut[m][i];

  // ---- A fragments straight from gmem ----
  const float* xg = x + ((size_t)(b * NM + m) * NV) * NT + tile * TT;
  const int trow = wid * 32 + gid;

  u32 Ah[2][4][4], Al[2][4][4];
  #pragma unroll
  for (int mt = 0; mt < 2; mt++){
    #pragma unroll
    for (int kt = 0; kt < 4; kt++){
      int r0 = trow + mt * 16;
      int r1 = r0 + 8;
      int v0 = kt * 16 + 2 * tig;
      int v8 = v0 + 8;
      float x00 = (v0     < NV) ? xg[(size_t)(v0    ) * NT + r0] : 0.f;
      float x01 = (v0 + 1 < NV) ? xg[(size_t)(v0 + 1) * NT + r0] : 0.f;
      float x10 = (v0     < NV) ? xg[(size_t)(v0    ) * NT + r1] : 0.f;
      float x11 = (v0 + 1 < NV) ? xg[(size_t)(v0 + 1) * NT + r1] : 0.f;
      float y00 = (v8     < NV) ? xg[(size_t)(v8    ) * NT + r0] : 0.f;
      float y01 = (v8 + 1 < NV) ? xg[(size_t)(v8 + 1) * NT + r0] : 0.f;
      float y10 = (v8     < NV) ? xg[(size_t)(v8    ) * NT + r1] : 0.f;
      float y11 = (v8 + 1 < NV) ? xg[(size_t)(v8 + 1) * NT + r1] : 0.f;
      split2(x00, x01, Ah[mt][kt][0], Al[mt][kt][0]);
      split2(x10, x11, Ah[mt][kt][1], Al[mt][kt][1]);
      split2(y00, y01, Ah[mt][kt][2], Al[mt][kt][2]);
      split2(y10, y11, Ah[mt][kt][3], Al[mt][kt][3]);
    }
  }

  __syncthreads();   // zeros visible before scatter

  // ---- stage P^T swizzled (coalesced gmem reads over w) ----
  const float* PAm = PA + m * NV * NV;
  for (int i = tid; i < NV * NV; i += TPB){
    int v = i / NV;
    int w = i - v * NV;           // consecutive across threads
    float p = PAm[i];             // PA[m][v][w]
    __nv_bfloat16 h = __float2bfloat16(p);
    float lo = p - __bfloat162float(h);
    __nv_bfloat16 hl = __float2bfloat16(lo);
    u32 off = (u32)w * 128u + (u32)(((v >> 3) ^ (w & 7)) * 16) + (u32)((v & 7) * 2);
    *(unsigned short*)(p_hi + off) = __bfloat16_as_ushort(h);
    *(unsigned short*)(p_lo + off) = __bfloat16_as_ushort(hl);
  }
  __syncthreads();

  // ---- fold conv + BN ----
  const float scale = bn_gamma[m] * rsqrtf(bn_var[m] + 1e-5f);
  const float A = conv_w[m] * scale;
  const float C = (conv_b[m] - bn_mean[m]) * scale + bn_beta[m];

  // ---- MMA + fused epilogue: D = Ah*Bh + Ah*Bl + Al*Bh; node_update per n-tile ----
  const u32 phib = smem_u32(p_hi);
  const u32 plob = smem_u32(p_lo);
  const int lm    = lane & 15;
  const int wrow8 = lm & 7;
  const int msel  = (lm >> 3) & 1;

  // per-row softmax accumulators: rows trow, trow+8, trow+16, trow+24
  float lr[4] = {0.f, 0.f, 0.f, 0.f};
  float ar[4] = {0.f, 0.f, 0.f, 0.f};

  #pragma unroll
  for (int nt = 0; nt < 7; nt++){
    float d0[4] = {0.f, 0.f, 0.f, 0.f};
    float d1[4] = {0.f, 0.f, 0.f, 0.f};
    #pragma unroll
    for (int kt = 0; kt < 4; kt++){
      int wrow  = nt * 8 + wrow8;
      int chunk = 2 * kt + msel;
      u32 boff  = (u32)wrow * 128u + (u32)((chunk ^ (wrow & 7)) * 16);
      u32 bh0, bh1, bl0, bl1;
      ldsm2(bh0, bh1, phib + boff);
      ldsm2(bl0, bl1, plob + boff);
      mma_bf16(d0, Ah[0][kt], bh0, bh1);
      mma_bf16(d1, Ah[1][kt], bh0, bh1);
      mma_bf16(d0, Ah[0][kt], bl0, bl1);
      mma_bf16(d1, Ah[1][kt], bl0, bl1);
      mma_bf16(d0, Al[0][kt], bh0, bh1);
      mma_bf16(d1, Al[1][kt], bh0, bh1);
    }
    // fused node updates; GUARD padded cols (w >= NV would contribute relu(C)!)
    int wc = nt * 8 + 2 * tig;
    if (wc < NV){
      node_update(d0[0], A, C, sLUT, lr[0], ar[0]);
      node_update(d0[2], A, C, sLUT, lr[1], ar[1]);
      node_update(d1[0], A, C, sLUT, lr[2], ar[2]);
      node_update(d1[2], A, C, sLUT, lr[3], ar[3]);
    }
    if (wc + 1 < NV){
      node_update(d0[1], A, C, sLUT, lr[0], ar[0]);
      node_update(d0[3], A, C, sLUT, lr[1], ar[1]);
      node_update(d1[1], A, C, sLUT, lr[2], ar[2]);
      node_update(d1[3], A, C, sLUT, lr[3], ar[3]);
    }
  }

  // ---- quad reduction over tig (cols of each row live in lanes tig=0..3) ----
  #pragma unroll
  for (int i = 0; i < 4; i++){
    lr[i] += __shfl_xor_sync(0xFFFFFFFFu, lr[i], 1);
    ar[i] += __shfl_xor_sync(0xFFFFFFFFu, ar[i], 1);
    lr[i] += __shfl_xor_sync(0xFFFFFFFFu, lr[i], 2);
    ar[i] += __shfl_xor_sync(0xFFFFFFFFu, ar[i], 2);
  }

  if (tig == 0){
    float* ob = out + (size_t)(b * NM + m) * NT + tile * TT + trow;
    ob[0]  = ar[0] / lr[0];
    ob[8]  = ar[1] / lr[1];
    ob[16] = ar[2] / lr[2];
    ob[24] = ar[3] / lr[3];
  }
}

extern "C" void kernel_launch(void* const* d_in, const int* in_sizes, int n_in,
                              void* d_out, int out_size)
{
  (void)in_sizes; (void)n_in; (void)out_size;
  lut_build<<<NM, 256>>>((const float*)d_in[8],  (const float*)d_in[9],
                         (const float*)d_in[10], (const float*)d_in[11]);
  ima_kernel<<<NB * NM * NTILE, TPB>>>(
      (const float*)d_in[0],  (const float*)d_in[1],
      (const float*)d_in[2],  (const float*)d_in[3],
      (const float*)d_in[4],  (const float*)d_in[5],
      (const float*)d_in[6],  (const float*)d_in[7],
      (float*)d_out);
}

// round 13
// speedup vs baseline: 2.3553x; 2.3553x over previous
#include <cuda_runtime.h>
#include <cuda_bf16.h>
#include <math.h>

#define NB 64
#define NT 512
#define NM 8
#define NV 50
#define TT  128          // timesteps per CTA tile
#define NTILE 4          // NT / TT
#define TPB 128
#define WPAD 56          // padded w (7 n-tiles of 8)
#define GP 51            // gbuf row pad (floats); stores guarded to wc<NV
#define LUTN 512
#define LUTF 512.0f

typedef unsigned int u32;

// Pre-split, pre-swizzled B images: [m][hi=0/lo=1][u32 slot]
__device__ __align__(16) u32 g_bimg[NM][2][WPAD * 32];
__device__ __align__(16) float2 g_lut[NM][LUTN];

// ---------------- helpers ----------------
__device__ __forceinline__ u32 smem_u32(const void* p){
  u32 a; asm("{ .reg .u64 t; cvta.to.shared.u64 t, %1; cvt.u32.u64 %0, t; }" : "=r"(a) : "l"(p));
  return a;
}
__device__ __forceinline__ float ex2f(float x){ float r; asm("ex2.approx.f32 %0, %1;" : "=f"(r) : "f"(x)); return r; }
__device__ __forceinline__ float rcpf(float x){ float r; asm("rcp.approx.f32 %0, %1;" : "=f"(r) : "f"(x)); return r; }

__device__ __forceinline__ void mma_bf16(float* d, const u32* a, u32 b0, u32 b1){
  asm volatile("mma.sync.aligned.m16n8k16.row.col.f32.bf16.bf16.f32 "
    "{%0,%1,%2,%3}, {%4,%5,%6,%7}, {%8,%9}, {%0,%1,%2,%3};"
    : "+f"(d[0]), "+f"(d[1]), "+f"(d[2]), "+f"(d[3])
    : "r"(a[0]), "r"(a[1]), "r"(a[2]), "r"(a[3]), "r"(b0), "r"(b1));
}
__device__ __forceinline__ void ldsm2(u32 &r0, u32 &r1, u32 addr){
  asm volatile("ldmatrix.sync.aligned.m8n8.x2.shared.b16 {%0,%1}, [%2];"
    : "=r"(r0), "=r"(r1) : "r"(addr));
}

// fast split: packed bf16 hi (rn) + packed bf16 of residual
__device__ __forceinline__ void split2f(float f0, float f1, u32 &hp, u32 &lp){
  u32 h; asm("cvt.rn.bf16x2.f32 %0, %1, %2;" : "=r"(h) : "f"(f1), "f"(f0));
  float b0 = __uint_as_float(h << 16);
  float b1 = __uint_as_float(h & 0xFFFF0000u);
  float l0 = f0 - b0;
  float l1 = f1 - b1;
  u32 l; asm("cvt.rn.bf16x2.f32 %0, %1, %2;" : "=r"(l) : "f"(l1), "f"(l0));
  hp = h; lp = l;
}

// ---------------- prep kernel: LUT + pre-split/pre-swizzled B images ----------------
__global__ void prep(const float* __restrict__ PA,
                     const float* __restrict__ w1, const float* __restrict__ b1,
                     const float* __restrict__ w2, const float* __restrict__ b2)
{
  const int m = blockIdx.x;
  const float LOG2E = 1.4426950408889634f;
  float W1[8], B1[8], W2[8];
  float bias = b2[m];
  float M = bias, lim = bias;
  #pragma unroll
  for (int j = 0; j < 8; j++){
    W1[j] = w1[m*8+j]; B1[j] = b1[m*8+j]; W2[j] = w2[m*8+j];
    M += fabsf(W2[j]);
    lim += W2[j] * (W1[j] > 0.f ? 1.f : (W1[j] < 0.f ? -1.f : tanhf(B1[j])));
  }
  M *= LOG2E; lim *= LOG2E;

  for (int i = threadIdx.x; i < LUTN; i += blockDim.x){
    float f0, f1;
    {
      float u = (float)i / LUTF;
      float h = u / (1.f - u);
      float s = bias;
      #pragma unroll
      for (int j = 0; j < 8; j++) s += W2[j] * tanhf(fmaf(h, W1[j], B1[j]));
      f0 = s * LOG2E;
    }
    if (i + 1 == LUTN) f1 = lim;
    else {
      float u = (float)(i + 1) / LUTF;
      float h = u / (1.f - u);
      float s = bias;
      #pragma unroll
      for (int j = 0; j < 8; j++) s += W2[j] * tanhf(fmaf(h, W1[j], B1[j]));
      f1 = s * LOG2E;
    }
    g_lut[m][i] = make_float2(f0 - M, f1 - f0);
  }

  // B image: inverse-swizzle gather; forward: byte = w*128 + ((v>>3)^(w&7))*16 + (v&7)*2
  const float* PAm = PA + m * NV * NV;
  for (int i = threadIdx.x; i < WPAD * 32; i += blockDim.x){
    int w  = i >> 5;
    int j0 = (i & 31) * 2;                        // u16 slot (even)
    int c  = j0 >> 3;                             // chunk 0..7
    int v0 = ((c ^ (w & 7)) << 3) | (j0 & 7);     // inverse swizzle
    int v1 = v0 + 1;                              // same chunk (j0 even)
    float p0 = (w < NV && v0 < NV) ? PAm[v0 * NV + w] : 0.f;
    float p1 = (w < NV && v1 < NV) ? PAm[v1 * NV + w] : 0.f;
    u32 hp, lp; split2f(p0, p1, hp, lp);
    g_bimg[m][0][i] = hp;
    g_bimg[m][1][i] = lp;
  }
}

// ---------------- main kernel ----------------
__device__ __forceinline__ void node_update(float gval, float A, float C,
                                            const float2* __restrict__ sLUT,
                                            float &l, float &acc)
{
  float h = fmaxf(fmaf(gval, A, C), 0.f);
  float r = rcpf(1.f + h);                 // r in (0,1]
  float q = fmaf(r, -LUTF, LUTF);          // q in (~-eps, 512)
  int   i = (int)q;                        // trunc: tiny negative -> 0
  i = min(i, LUTN - 1);                    // overflow insurance only
  float fr = q - (float)i;
  float2 e = sLUT[i];
  float p = ex2f(fmaf(fr, e.y, e.x));
  l += p;
  acc = fmaf(h, p, acc);
}

__global__ void __launch_bounds__(TPB)
ima_kernel(const float* __restrict__ x,
           const float* __restrict__ conv_w, const float* __restrict__ conv_b,
           const float* __restrict__ bn_gamma, const float* __restrict__ bn_beta,
           const float* __restrict__ bn_mean,  const float* __restrict__ bn_var,
           float* __restrict__ out)
{
  __shared__ __align__(128) u32 pimg[2][WPAD * 32];   // 14 KB (hi, lo)
  __shared__ float  gbuf[TT * GP];                    // 25.5 KB
  __shared__ __align__(16) float2 sLUT[LUTN];         // 4 KB   (total ~43.5 KB)

  const int tid  = threadIdx.x;
  const int wid  = tid >> 5;
  const int lane = tid & 31;
  const int gid  = lane >> 2;
  const int tig  = lane & 3;

  const int blk  = blockIdx.x;      // 0..2047
  const int tile = blk & (NTILE - 1);
  const int bm   = blk / NTILE;
  const int m    = bm & (NM - 1);
  const int b    = bm / NM;

  // ---- stage B images + LUT with wide copies ----
  {
    const uint4* src = (const uint4*)&g_bimg[m][0][0];   // 896 uint4
    uint4* dst = (uint4*)&pimg[0][0];
    #pragma unroll
    for (int i = tid; i < 896; i += TPB) dst[i] = src[i];
    const uint4* ls = (const uint4*)&g_lut[m][0];        // 256 uint4
    uint4* ld = (uint4*)sLUT;
    #pragma unroll
    for (int i = tid; i < 256; i += TPB) ld[i] = ls[i];
  }

  // ---- A fragments straight from gmem ----
  const float* xg = x + ((size_t)(b * NM + m) * NV) * NT + tile * TT;
  const int trow = wid * 32 + gid;

  u32 Ah[2][4][4], Al[2][4][4];
  #pragma unroll
  for (int mt = 0; mt < 2; mt++){
    #pragma unroll
    for (int kt = 0; kt < 4; kt++){
      int r0 = trow + mt * 16;
      int r1 = r0 + 8;
      int v0 = kt * 16 + 2 * tig;
      int v8 = v0 + 8;
      float x00 = (v0     < NV) ? xg[(size_t)(v0    ) * NT + r0] : 0.f;
      float x01 = (v0 + 1 < NV) ? xg[(size_t)(v0 + 1) * NT + r0] : 0.f;
      float x10 = (v0     < NV) ? xg[(size_t)(v0    ) * NT + r1] : 0.f;
      float x11 = (v0 + 1 < NV) ? xg[(size_t)(v0 + 1) * NT + r1] : 0.f;
      float y00 = (v8     < NV) ? xg[(size_t)(v8    ) * NT + r0] : 0.f;
      float y01 = (v8 + 1 < NV) ? xg[(size_t)(v8 + 1) * NT + r0] : 0.f;
      float y10 = (v8     < NV) ? xg[(size_t)(v8    ) * NT + r1] : 0.f;
      float y11 = (v8 + 1 < NV) ? xg[(size_t)(v8 + 1) * NT + r1] : 0.f;
      split2f(x00, x01, Ah[mt][kt][0], Al[mt][kt][0]);
      split2f(x10, x11, Ah[mt][kt][1], Al[mt][kt][1]);
      split2f(y00, y01, Ah[mt][kt][2], Al[mt][kt][2]);
      split2f(y10, y11, Ah[mt][kt][3], Al[mt][kt][3]);
    }
  }

  __syncthreads();

  // ---- MMA main: D = Ah*Bh + Ah*Bl + Al*Bh ----
  const u32 phib = smem_u32(&pimg[0][0]);
  const u32 plob = smem_u32(&pimg[1][0]);
  const int lm    = lane & 15;
  const int wrow8 = lm & 7;
  const int msel  = (lm >> 3) & 1;

  #pragma unroll
  for (int nt = 0; nt < 7; nt++){
    float d0[4] = {0.f, 0.f, 0.f, 0.f};
    float d1[4] = {0.f, 0.f, 0.f, 0.f};
    #pragma unroll
    for (int kt = 0; kt < 4; kt++){
      int wrow  = nt * 8 + wrow8;
      int chunk = 2 * kt + msel;
      u32 boff  = (u32)wrow * 128u + (u32)((chunk ^ (wrow & 7)) * 16);
      u32 bh0, bh1, bl0, bl1;
      ldsm2(bh0, bh1, phib + boff);
      ldsm2(bl0, bl1, plob + boff);
      mma_bf16(d0, Ah[0][kt], bh0, bh1);
      mma_bf16(d1, Ah[1][kt], bh0, bh1);
      mma_bf16(d0, Ah[0][kt], bl0, bl1);
      mma_bf16(d1, Ah[1][kt], bl0, bl1);
      mma_bf16(d0, Al[0][kt], bh0, bh1);
      mma_bf16(d1, Al[1][kt], bh0, bh1);
    }
    int wc = nt * 8 + 2 * tig;
    if (wc < NV){
      gbuf[(trow     ) * GP + wc] = d0[0];
      gbuf[(trow +  8) * GP + wc] = d0[2];
      gbuf[(trow + 16) * GP + wc] = d1[0];
      gbuf[(trow + 24) * GP + wc] = d1[2];
    }
    if (wc + 1 < NV){
      gbuf[(trow     ) * GP + wc + 1] = d0[1];
      gbuf[(trow +  8) * GP + wc + 1] = d0[3];
      gbuf[(trow + 16) * GP + wc + 1] = d1[1];
      gbuf[(trow + 24) * GP + wc + 1] = d1[3];
    }
  }

  __syncthreads();

  // ---- epilogue: one timestep per thread ----
  const float scale = bn_gamma[m] * rsqrtf(bn_var[m] + 1e-5f);
  const float A = conv_w[m] * scale;
  const float C = (conv_b[m] - bn_mean[m]) * scale + bn_beta[m];

  float l = 0.f, acc = 0.f;
  const float* grow = &gbuf[tid * GP];
  #pragma unroll
  for (int c = 0; c < NV; c++)
    node_update(grow[c], A, C, sLUT, l, acc);

  out[(size_t)(b * NM + m) * NT + tile * TT + tid] = acc / l;
}

extern "C" void kernel_launch(void* const* d_in, const int* in_sizes, int n_in,
                              void* d_out, int out_size)
{
  (void)in_sizes; (void)n_in; (void)out_size;
  prep<<<NM, 256>>>((const float*)d_in[1],
                    (const float*)d_in[8],  (const float*)d_in[9],
                    (const float*)d_in[10], (const float*)d_in[11]);
  ima_kernel<<<NB * NM * NTILE, TPB>>>(
      (const float*)d_in[0],
      (const float*)d_in[2],  (const float*)d_in[3],
      (const float*)d_in[4],  (const float*)d_in[5],
      (const float*)d_in[6],  (const float*)d_in[7],
      (float*)d_out);
}

// round 16
// speedup vs baseline: 2.4964x; 1.0599x over previous
#include <cuda_runtime.h>
#include <cuda_bf16.h>
#include <math.h>

#define NB 64
#define NT 512
#define NM 8
#define NV 50
#define TT  128          // timesteps per CTA tile
#define NTILE 4          // NT / TT
#define TPB 128
#define WPAD 56          // padded w (7 n-tiles of 8)
#define GP 51            // gbuf row pad (floats); stores guarded to wc<NV
#define LUTN 512
#define LUTF 512.0f
#define LUT_U4 ((LUTN * 8) / 16)   // 256 uint4 -- DO NOT hand-edit (R14/R15 bug)
#define PREPSPLIT 4

typedef unsigned int u32;

// Pre-split, pre-swizzled B images: [m][hi=0/lo=1][u32 slot]
__device__ __align__(16) u32 g_bimg[NM][2][WPAD * 32];
__device__ __align__(16) float2 g_lut[NM][LUTN];

// ---------------- helpers ----------------
__device__ __forceinline__ u32 smem_u32(const void* p){
  u32 a; asm("{ .reg .u64 t; cvta.to.shared.u64 t, %1; cvt.u32.u64 %0, t; }" : "=r"(a) : "l"(p));
  return a;
}
__device__ __forceinline__ float ex2f(float x){ float r; asm("ex2.approx.f32 %0, %1;" : "=f"(r) : "f"(x)); return r; }
__device__ __forceinline__ float rcpf(float x){ float r; asm("rcp.approx.f32 %0, %1;" : "=f"(r) : "f"(x)); return r; }

__device__ __forceinline__ void mma_bf16(float* d, const u32* a, u32 b0, u32 b1){
  asm volatile("mma.sync.aligned.m16n8k16.row.col.f32.bf16.bf16.f32 "
    "{%0,%1,%2,%3}, {%4,%5,%6,%7}, {%8,%9}, {%0,%1,%2,%3};"
    : "+f"(d[0]), "+f"(d[1]), "+f"(d[2]), "+f"(d[3])
    : "r"(a[0]), "r"(a[1]), "r"(a[2]), "r"(a[3]), "r"(b0), "r"(b1));
}
// x4 ldmatrix: matrices 0,1 addressed by lanes 0-15 (hi image), matrices 2,3 by lanes 16-31 (lo image).
__device__ __forceinline__ void ldsm4(u32 &r0, u32 &r1, u32 &r2, u32 &r3, u32 addr){
  asm volatile("ldmatrix.sync.aligned.m8n8.x4.shared.b16 {%0,%1,%2,%3}, [%4];"
    : "=r"(r0), "=r"(r1), "=r"(r2), "=r"(r3) : "r"(addr));
}

// fast split: packed bf16 hi (rn) + packed bf16 of residual
__device__ __forceinline__ void split2f(float f0, float f1, u32 &hp, u32 &lp){
  u32 h; asm("cvt.rn.bf16x2.f32 %0, %1, %2;" : "=r"(h) : "f"(f1), "f"(f0));
  float b0 = __uint_as_float(h << 16);
  float b1 = __uint_as_float(h & 0xFFFF0000u);
  float l0 = f0 - b0;
  float l1 = f1 - b1;
  u32 l; asm("cvt.rn.bf16x2.f32 %0, %1, %2;" : "=r"(l) : "f"(l1), "f"(l0));
  hp = h; lp = l;
}

// ---------------- prep kernel: LUT + pre-split/pre-swizzled B images ----------------
// grid (NM, PREPSPLIT): each block does 1/PREPSPLIT of its module's LUT and B image.
__global__ void prep(const float* __restrict__ PA,
                     const float* __restrict__ w1, const float* __restrict__ b1,
                     const float* __restrict__ w2, const float* __restrict__ b2)
{
  const int m    = blockIdx.x;
  const int part = blockIdx.y;
  const float LOG2E = 1.4426950408889634f;
  float W1[8], B1[8], W2[8];
  float bias = b2[m];
  float M = bias, lim = bias;
  #pragma unroll
  for (int j = 0; j < 8; j++){
    W1[j] = w1[m*8+j]; B1[j] = b1[m*8+j]; W2[j] = w2[m*8+j];
    M += fabsf(W2[j]);
    lim += W2[j] * (W1[j] > 0.f ? 1.f : (W1[j] < 0.f ? -1.f : tanhf(B1[j])));
  }
  M *= LOG2E; lim *= LOG2E;

  const int lchunk = LUTN / PREPSPLIT;
  for (int i = part * lchunk + threadIdx.x; i < (part + 1) * lchunk; i += blockDim.x){
    float f0, f1;
    {
      float u = (float)i / LUTF;
      float h = u / (1.f - u);
      float s = bias;
      #pragma unroll
      for (int j = 0; j < 8; j++) s += W2[j] * tanhf(fmaf(h, W1[j], B1[j]));
      f0 = s * LOG2E;
    }
    if (i + 1 == LUTN) f1 = lim;
    else {
      float u = (float)(i + 1) / LUTF;
      float h = u / (1.f - u);
      float s = bias;
      #pragma unroll
      for (int j = 0; j < 8; j++) s += W2[j] * tanhf(fmaf(h, W1[j], B1[j]));
      f1 = s * LOG2E;
    }
    g_lut[m][i] = make_float2(f0 - M, f1 - f0);
  }

  // B image: inverse-swizzle gather; forward: byte = w*128 + ((v>>3)^(w&7))*16 + (v&7)*2
  const float* PAm = PA + m * NV * NV;
  const int bchunk = (WPAD * 32) / PREPSPLIT;
  for (int i = part * bchunk + threadIdx.x; i < (part + 1) * bchunk; i += blockDim.x){
    int w  = i >> 5;
    int j0 = (i & 31) * 2;                        // u16 slot (even)
    int c  = j0 >> 3;                             // chunk 0..7
    int v0 = ((c ^ (w & 7)) << 3) | (j0 & 7);     // inverse swizzle
    int v1 = v0 + 1;                              // same chunk (j0 even)
    float p0 = (w < NV && v0 < NV) ? PAm[v0 * NV + w] : 0.f;
    float p1 = (w < NV && v1 < NV) ? PAm[v1 * NV + w] : 0.f;
    u32 hp, lp; split2f(p0, p1, hp, lp);
    g_bimg[m][0][i] = hp;
    g_bimg[m][1][i] = lp;
  }
}

// ---------------- main kernel ----------------
__device__ __forceinline__ void node_update(float gval, float A, float C,
                                            const float2* __restrict__ sLUT,
                                            float &l, float &acc)
{
  float h = fmaxf(fmaf(gval, A, C), 0.f);
  float r = rcpf(1.f + h);                 // r in (0,1]
  float q = fmaf(r, -LUTF, LUTF);          // q in (~-eps, 512)
  int   i = (int)q;                        // trunc: tiny negative -> 0
  i = min(i, LUTN - 1);                    // overflow insurance only
  float fr = q - (float)i;
  float2 e = sLUT[i];
  float p = ex2f(fmaf(fr, e.y, e.x));
  l += p;
  acc = fmaf(h, p, acc);
}

__global__ void __launch_bounds__(TPB)
ima_kernel(const float* __restrict__ x,
           const float* __restrict__ conv_w, const float* __restrict__ conv_b,
           const float* __restrict__ bn_gamma, const float* __restrict__ bn_beta,
           const float* __restrict__ bn_mean,  const float* __restrict__ bn_var,
           float* __restrict__ out)
{
  __shared__ __align__(128) u32 pimg[2][WPAD * 32];   // 14 KB (hi, lo contiguous)
  __shared__ float  gbuf[TT * GP];                    // 25.5 KB
  __shared__ __align__(16) float2 sLUT[LUTN];         // 4 KB   (total ~43.5 KB)

  const int tid  = threadIdx.x;
  const int wid  = tid >> 5;
  const int lane = tid & 31;
  const int gid  = lane >> 2;
  const int tig  = lane & 3;

  const int blk  = blockIdx.x;      // 0..2047
  const int tile = blk & (NTILE - 1);
  const int bm   = blk / NTILE;
  const int m    = bm & (NM - 1);
  const int b    = bm / NM;

  // ---- stage B images + LUT with wide copies ----
  {
    const uint4* src = (const uint4*)&g_bimg[m][0][0];   // 896 uint4
    uint4* dst = (uint4*)&pimg[0][0];
    #pragma unroll
    for (int i = tid; i < 896; i += TPB) dst[i] = src[i];
    const uint4* ls = (const uint4*)&g_lut[m][0];        // LUT_U4 = 256 uint4 (FULL LUT)
    uint4* ld = (uint4*)sLUT;
    #pragma unroll
    for (int i = tid; i < LUT_U4; i += TPB) ld[i] = ls[i];
  }

  // ---- A fragments straight from gmem ----
  const float* xg = x + ((size_t)(b * NM + m) * NV) * NT + tile * TT;
  const int trow = wid * 32 + gid;

  u32 Ah[2][4][4], Al[2][4][4];
  #pragma unroll
  for (int mt = 0; mt < 2; mt++){
    #pragma unroll
    for (int kt = 0; kt < 4; kt++){
      int r0 = trow + mt * 16;
      int r1 = r0 + 8;
      int v0 = kt * 16 + 2 * tig;
      int v8 = v0 + 8;
      float x00 = (v0     < NV) ? xg[(size_t)(v0    ) * NT + r0] : 0.f;
      float x01 = (v0 + 1 < NV) ? xg[(size_t)(v0 + 1) * NT + r0] : 0.f;
      float x10 = (v0     < NV) ? xg[(size_t)(v0    ) * NT + r1] : 0.f;
      float x11 = (v0 + 1 < NV) ? xg[(size_t)(v0 + 1) * NT + r1] : 0.f;
      float y00 = (v8     < NV) ? xg[(size_t)(v8    ) * NT + r0] : 0.f;
      float y01 = (v8 + 1 < NV) ? xg[(size_t)(v8 + 1) * NT + r0] : 0.f;
      float y10 = (v8     < NV) ? xg[(size_t)(v8    ) * NT + r1] : 0.f;
      float y11 = (v8 + 1 < NV) ? xg[(size_t)(v8 + 1) * NT + r1] : 0.f;
      split2f(x00, x01, Ah[mt][kt][0], Al[mt][kt][0]);
      split2f(x10, x11, Ah[mt][kt][1], Al[mt][kt][1]);
      split2f(y00, y01, Ah[mt][kt][2], Al[mt][kt][2]);
      split2f(y10, y11, Ah[mt][kt][3], Al[mt][kt][3]);
    }
  }

  __syncthreads();

  // ---- MMA main: D = Ah*Bh + Ah*Bl + Al*Bh ----
  // One ldmatrix.x4 per (nt,kt): lanes 0-15 address the hi image (matrices 0,1),
  // lanes 16-31 address the lo image (matrices 2,3). Fragment layout identical to ldsm2 pair.
  const u32 pbase = smem_u32(&pimg[0][0]);
  const u32 lsel  = (lane & 16) ? (u32)(WPAD * 32 * 4) : 0u;   // +7168 B -> lo image
  const int wrow8 = lane & 7;
  const int msel  = (lane >> 3) & 1;

  #pragma unroll
  for (int nt = 0; nt < 7; nt++){
    float d0[4] = {0.f, 0.f, 0.f, 0.f};
    float d1[4] = {0.f, 0.f, 0.f, 0.f};
    #pragma unroll
    for (int kt = 0; kt < 4; kt++){
      int wrow  = nt * 8 + wrow8;
      int chunk = 2 * kt + msel;
      u32 addr  = pbase + lsel + (u32)wrow * 128u + (u32)((chunk ^ (wrow & 7)) * 16);
      u32 bh0, bh1, bl0, bl1;
      ldsm4(bh0, bh1, bl0, bl1, addr);
      mma_bf16(d0, Ah[0][kt], bh0, bh1);
      mma_bf16(d1, Ah[1][kt], bh0, bh1);
      mma_bf16(d0, Ah[0][kt], bl0, bl1);
      mma_bf16(d1, Ah[1][kt], bl0, bl1);
      mma_bf16(d0, Al[0][kt], bh0, bh1);
      mma_bf16(d1, Al[1][kt], bh0, bh1);
    }
    // wc is always even, so wc+1 < NV covers both columns with one predicate.
    int wc = nt * 8 + 2 * tig;
    if (wc + 1 < NV){
      gbuf[(trow     ) * GP + wc    ] = d0[0];
      gbuf[(trow     ) * GP + wc + 1] = d0[1];
      gbuf[(trow +  8) * GP + wc    ] = d0[2];
      gbuf[(trow +  8) * GP + wc + 1] = d0[3];
      gbuf[(trow + 16) * GP + wc    ] = d1[0];
      gbuf[(trow + 16) * GP + wc + 1] = d1[1];
      gbuf[(trow + 24) * GP + wc    ] = d1[2];
      gbuf[(trow + 24) * GP + wc + 1] = d1[3];
    }
  }

  __syncthreads();

  // ---- epilogue: one timestep per thread ----
  const float scale = bn_gamma[m] * rsqrtf(bn_var[m] + 1e-5f);
  const float A = conv_w[m] * scale;
  const float C = (conv_b[m] - bn_mean[m]) * scale + bn_beta[m];

  float l = 0.f, acc = 0.f;
  const float* grow = &gbuf[tid * GP];
  #pragma unroll
  for (int c = 0; c < NV; c++)
    node_update(grow[c], A, C, sLUT, l, acc);

  out[(size_t)(b * NM + m) * NT + tile * TT + tid] = acc / l;
}

extern "C" void kernel_launch(void* const* d_in, const int* in_sizes, int n_in,
                              void* d_out, int out_size)
{
  (void)in_sizes; (void)n_in; (void)out_size;
  dim3 pgrid(NM, PREPSPLIT);
  prep<<<pgrid, 256>>>((const float*)d_in[1],
                       (const float*)d_in[8],  (const float*)d_in[9],
                       (const float*)d_in[10], (const float*)d_in[11]);
  ima_kernel<<<NB * NM * NTILE, TPB>>>(
      (const float*)d_in[0],
      (const float*)d_in[2],  (const float*)d_in[3],
      (const float*)d_in[4],  (const float*)d_in[5],
      (const float*)d_in[6],  (const float*)d_in[7],
      (float*)d_out);
}

// round 17
// speedup vs baseline: 2.5032x; 1.0027x over previous
#include <cuda_runtime.h>
#include <cuda_bf16.h>
#include <math.h>

#define NB 64
#define NT 512
#define NM 8
#define NV 50
#define TT  128          // timesteps per CTA tile
#define NTILE 4          // NT / TT
#define TPB 128
#define WPAD 56          // padded w (7 n-tiles of 8)
#define GP 51            // gbuf row pad (floats); stores guarded to wc<NV
#define LUTN 256
#define LUTF 256.0f
#define LUT_U4 ((LUTN * 8) / 16)   // uint4 count of full LUT -- do not hand-edit
#define PREPSPLIT 4

// A-stage image geometry: rows = v (56, rows 50..55 zero), 272 B row stride
// (17 x 16B -> 8 consecutive rows hit 8 distinct bank groups; ldmatrix-safe)
#define AROWS 56
#define ASTRIDE 272
#define AIMG (AROWS * ASTRIDE)     // 15232 B per image
#define UBUF_BYTES (2 * AIMG)      // 30464 B; gbuf (26112 B) aliases this

typedef unsigned int u32;

__device__ __align__(16) u32 g_bimg[NM][2][WPAD * 32];
__device__ __align__(16) float2 g_lut[NM][LUTN];

// ---------------- helpers ----------------
__device__ __forceinline__ u32 smem_u32(const void* p){
  u32 a; asm("{ .reg .u64 t; cvta.to.shared.u64 t, %1; cvt.u32.u64 %0, t; }" : "=r"(a) : "l"(p));
  return a;
}
__device__ __forceinline__ float ex2f(float x){ float r; asm("ex2.approx.f32 %0, %1;" : "=f"(r) : "f"(x)); return r; }
__device__ __forceinline__ float rcpf(float x){ float r; asm("rcp.approx.f32 %0, %1;" : "=f"(r) : "f"(x)); return r; }

__device__ __forceinline__ void mma_bf16(float* d, const u32* a, u32 b0, u32 b1){
  asm volatile("mma.sync.aligned.m16n8k16.row.col.f32.bf16.bf16.f32 "
    "{%0,%1,%2,%3}, {%4,%5,%6,%7}, {%8,%9}, {%0,%1,%2,%3};"
    : "+f"(d[0]), "+f"(d[1]), "+f"(d[2]), "+f"(d[3])
    : "r"(a[0]), "r"(a[1]), "r"(a[2]), "r"(a[3]), "r"(b0), "r"(b1));
}
// B path (proven R16): non-transposed x4; lanes 0-15 hi image, 16-31 lo image.
__device__ __forceinline__ void ldsm4(u32 &r0, u32 &r1, u32 &r2, u32 &r3, u32 addr){
  asm volatile("ldmatrix.sync.aligned.m8n8.x4.shared.b16 {%0,%1,%2,%3}, [%4];"
    : "=r"(r0), "=r"(r1), "=r"(r2), "=r"(r3) : "r"(addr));
}
// A path (new): transposed ldmatrix. Stored M[v][t]; thread l gets
// {M[2(l&3)][l>>2], M[2(l&3)+1][l>>2]} per matrix = row-major A fragment.
__device__ __forceinline__ void ldsm4t(u32 &r0, u32 &r1, u32 &r2, u32 &r3, u32 addr){
  asm volatile("ldmatrix.sync.aligned.m8n8.x4.trans.shared.b16 {%0,%1,%2,%3}, [%4];"
    : "=r"(r0), "=r"(r1), "=r"(r2), "=r"(r3) : "r"(addr));
}
__device__ __forceinline__ void ldsm2t(u32 &r0, u32 &r1, u32 addr){
  asm volatile("ldmatrix.sync.aligned.m8n8.x2.trans.shared.b16 {%0,%1}, [%2];"
    : "=r"(r0), "=r"(r1) : "r"(addr));
}

// fast split: packed bf16 hi (rn) + packed bf16 of residual
__device__ __forceinline__ void split2f(float f0, float f1, u32 &hp, u32 &lp){
  u32 h; asm("cvt.rn.bf16x2.f32 %0, %1, %2;" : "=r"(h) : "f"(f1), "f"(f0));
  float b0 = __uint_as_float(h << 16);
  float b1 = __uint_as_float(h & 0xFFFF0000u);
  float l0 = f0 - b0;
  float l1 = f1 - b1;
  u32 l; asm("cvt.rn.bf16x2.f32 %0, %1, %2;" : "=r"(l) : "f"(l1), "f"(l0));
  hp = h; lp = l;
}

// ---------------- prep kernel ----------------
__global__ void prep(const float* __restrict__ PA,
                     const float* __restrict__ w1, const float* __restrict__ b1,
                     const float* __restrict__ w2, const float* __restrict__ b2)
{
  const int m    = blockIdx.x;
  const int part = blockIdx.y;
  const float LOG2E = 1.4426950408889634f;
  float W1[8], B1[8], W2[8];
  float bias = b2[m];
  float M = bias, lim = bias;
  #pragma unroll
  for (int j = 0; j < 8; j++){
    W1[j] = w1[m*8+j]; B1[j] = b1[m*8+j]; W2[j] = w2[m*8+j];
    M += fabsf(W2[j]);
    lim += W2[j] * (W1[j] > 0.f ? 1.f : (W1[j] < 0.f ? -1.f : tanhf(B1[j])));
  }
  M *= LOG2E; lim *= LOG2E;

  const int lchunk = LUTN / PREPSPLIT;
  for (int i = part * lchunk + threadIdx.x; i < (part + 1) * lchunk; i += blockDim.x){
    float f0, f1;
    {
      float u = (float)i / LUTF;
      float h = u / (1.f - u);
      float s = bias;
      #pragma unroll
      for (int j = 0; j < 8; j++) s += W2[j] * tanhf(fmaf(h, W1[j], B1[j]));
      f0 = s * LOG2E;
    }
    if (i + 1 == LUTN) f1 = lim;
    else {
      float u = (float)(i + 1) / LUTF;
      float h = u / (1.f - u);
      float s = bias;
      #pragma unroll
      for (int j = 0; j < 8; j++) s += W2[j] * tanhf(fmaf(h, W1[j], B1[j]));
      f1 = s * LOG2E;
    }
    g_lut[m][i] = make_float2(f0 - M, f1 - f0);
  }

  // B image: inverse-swizzle gather; forward: byte = w*128 + ((v>>3)^(w&7))*16 + (v&7)*2
  const float* PAm = PA + m * NV * NV;
  const int bchunk = (WPAD * 32) / PREPSPLIT;
  for (int i = part * bchunk + threadIdx.x; i < (part + 1) * bchunk; i += blockDim.x){
    int w  = i >> 5;
    int j0 = (i & 31) * 2;
    int c  = j0 >> 3;
    int v0 = ((c ^ (w & 7)) << 3) | (j0 & 7);
    int v1 = v0 + 1;
    float p0 = (w < NV && v0 < NV) ? PAm[v0 * NV + w] : 0.f;
    float p1 = (w < NV && v1 < NV) ? PAm[v1 * NV + w] : 0.f;
    u32 hp, lp; split2f(p0, p1, hp, lp);
    g_bimg[m][0][i] = hp;
    g_bimg[m][1][i] = lp;
  }
}

// ---------------- main kernel ----------------
__device__ __forceinline__ void node_update(float gval, float A, float C,
                                            const float2* __restrict__ sLUT,
                                            float &l, float &acc)
{
  float h = fmaxf(fmaf(gval, A, C), 0.f);
  float r = rcpf(1.f + h);
  float q = fmaf(r, -LUTF, LUTF);
  int   i = (int)q;
  i = min(i, LUTN - 1);
  float fr = q - (float)i;
  float2 e = sLUT[i];
  float p = ex2f(fmaf(fr, e.y, e.x));
  l += p;
  acc = fmaf(h, p, acc);
}

__global__ void __launch_bounds__(TPB)
ima_kernel(const float* __restrict__ x,
           const float* __restrict__ conv_w, const float* __restrict__ conv_b,
           const float* __restrict__ bn_gamma, const float* __restrict__ bn_beta,
           const float* __restrict__ bn_mean,  const float* __restrict__ bn_var,
           float* __restrict__ out)
{
  __shared__ __align__(128) u32 pimg[2][WPAD * 32];        // 14336 B
  __shared__ __align__(128) unsigned char ubuf[UBUF_BYTES]; // 30464 B: A-stage, then gbuf
  __shared__ __align__(16) float2 sLUT[LUTN];               // 2048 B  (total ~46.8 KB)

  const int tid  = threadIdx.x;
  const int wid  = tid >> 5;
  const int lane = tid & 31;
  const int gid  = lane >> 2;
  const int tig  = lane & 3;

  const int blk  = blockIdx.x;      // 0..2047
  const int tile = blk & (NTILE - 1);
  const int bm   = blk / NTILE;
  const int m    = bm & (NM - 1);
  const int b    = bm / NM;

  // ---- stage B images + LUT with wide copies ----
  {
    const uint4* src = (const uint4*)&g_bimg[m][0][0];   // 896 uint4
    uint4* dst = (uint4*)&pimg[0][0];
    #pragma unroll
    for (int i = tid; i < 896; i += TPB) dst[i] = src[i];
    const uint4* ls = (const uint4*)&g_lut[m][0];        // LUT_U4 uint4 (FULL LUT)
    uint4* ld = (uint4*)sLUT;
    #pragma unroll
    for (int i = tid; i < LUT_U4; i += TPB) ld[i] = ls[i];
  }

  // ---- stage x -> A images (coalesced float4 loads, conflict-free STS.64) ----
  // ubuf layout: hi image at 0, lo image at AIMG; row v at v*ASTRIDE, t*2 bytes.
  {
    const float4* xg4 = (const float4*)(x + ((size_t)(b * NM + m) * NV) * NT + tile * TT);
    #pragma unroll
    for (int i = tid; i < NV * 32; i += TPB){   // 1600 float4 = 50 rows x 32
      int v  = i >> 5;
      int tq = i & 31;
      float4 f = xg4[v * (NT / 4) + tq];
      u32 h0, l0, h1, l1;
      split2f(f.x, f.y, h0, l0);
      split2f(f.z, f.w, h1, l1);
      u32 off = (u32)v * ASTRIDE + (u32)tq * 8;
      *(uint2*)(ubuf + off)        = make_uint2(h0, h1);
      *(uint2*)(ubuf + AIMG + off) = make_uint2(l0, l1);
    }
    // zero pad rows 50..55 of both images (408 u32 each)
    #pragma unroll
    for (int i = tid; i < 816; i += TPB){
      int img = (i >= 408);
      int j   = img ? i - 408 : i;
      *(u32*)(ubuf + img * AIMG + 50 * ASTRIDE + j * 4) = 0u;
    }
  }
  __syncthreads();

  // ---- A fragments via ldmatrix.trans from staged images ----
  const u32 abase = smem_u32(ubuf);
  const int ag  = lane >> 3;        // 0..3
  const int ar8 = lane & 7;

  u32 Ah[2][4][4], Al[2][4][4];
  #pragma unroll
  for (int mt = 0; mt < 2; mt++){
    const u32 toff = (u32)((wid * 32 + mt * 16) * 2) + (u32)((ag & 1) * 16);
    #pragma unroll
    for (int kt = 0; kt < 3; kt++){
      u32 voff = (u32)((kt * 16 + (ag >> 1) * 8 + ar8) * ASTRIDE);
      ldsm4t(Ah[mt][kt][0], Ah[mt][kt][1], Ah[mt][kt][2], Ah[mt][kt][3], abase + voff + toff);
      ldsm4t(Al[mt][kt][0], Al[mt][kt][1], Al[mt][kt][2], Al[mt][kt][3], abase + AIMG + voff + toff);
    }
    {  // kt = 3: only v 48..55 exist (50..55 zero); m2/m3 (v56..63) are all-zero
      u32 voff = (u32)((48 + ar8) * ASTRIDE);
      ldsm2t(Ah[mt][3][0], Ah[mt][3][1], abase + voff + toff);
      ldsm2t(Al[mt][3][0], Al[mt][3][1], abase + AIMG + voff + toff);
      Ah[mt][3][2] = 0u; Ah[mt][3][3] = 0u;
      Al[mt][3][2] = 0u; Al[mt][3][3] = 0u;
    }
  }
  __syncthreads();   // all warps done reading ubuf before gbuf stores overwrite it

  float* gbuf = (float*)ubuf;   // 128 x 51 floats = 26112 B <= UBUF_BYTES

  // ---- MMA main: D = Ah*Bh + Ah*Bl + Al*Bh ----
  const u32 pbase = smem_u32(&pimg[0][0]);
  const u32 lsel  = (lane & 16) ? (u32)(WPAD * 32 * 4) : 0u;
  const int wrow8 = lane & 7;
  const int msel  = (lane >> 3) & 1;
  const int trow  = wid * 32 + gid;

  #pragma unroll
  for (int nt = 0; nt < 7; nt++){
    float d0[4] = {0.f, 0.f, 0.f, 0.f};
    float d1[4] = {0.f, 0.f, 0.f, 0.f};
    #pragma unroll
    for (int kt = 0; kt < 4; kt++){
      int wrow  = nt * 8 + wrow8;
      int chunk = 2 * kt + msel;
      u32 addr  = pbase + lsel + (u32)wrow * 128u + (u32)((chunk ^ (wrow & 7)) * 16);
      u32 bh0, bh1, bl0, bl1;
      ldsm4(bh0, bh1, bl0, bl1, addr);
      mma_bf16(d0, Ah[0][kt], bh0, bh1);
      mma_bf16(d1, Ah[1][kt], bh0, bh1);
      mma_bf16(d0, Ah[0][kt], bl0, bl1);
      mma_bf16(d1, Ah[1][kt], bl0, bl1);
      mma_bf16(d0, Al[0][kt], bh0, bh1);
      mma_bf16(d1, Al[1][kt], bh0, bh1);
    }
    int wc = nt * 8 + 2 * tig;        // always even
    if (wc + 1 < NV){
      gbuf[(trow     ) * GP + wc    ] = d0[0];
      gbuf[(trow     ) * GP + wc + 1] = d0[1];
      gbuf[(trow +  8) * GP + wc    ] = d0[2];
      gbuf[(trow +  8) * GP + wc + 1] = d0[3];
      gbuf[(trow + 16) * GP + wc    ] = d1[0];
      gbuf[(trow + 16) * GP + wc + 1] = d1[1];
      gbuf[(trow + 24) * GP + wc    ] = d1[2];
      gbuf[(trow + 24) * GP + wc + 1] = d1[3];
    }
  }

  __syncthreads();

  // ---- epilogue: one timestep per thread ----
  const float scale = bn_gamma[m] * rsqrtf(bn_var[m] + 1e-5f);
  const float A = conv_w[m] * scale;
  const float C = (conv_b[m] - bn_mean[m]) * scale + bn_beta[m];

  float l = 0.f, acc = 0.f;
  const float* grow = &gbuf[tid * GP];
  #pragma unroll
  for (int c = 0; c < NV; c++)
    node_update(grow[c], A, C, sLUT, l, acc);

  out[(size_t)(b * NM + m) * NT + tile * TT + tid] = acc / l;
}

extern "C" void kernel_launch(void* const* d_in, const int* in_sizes, int n_in,
                              void* d_out, int out_size)
{
  (void)in_sizes; (void)n_in; (void)out_size;
  dim3 pgrid(NM, PREPSPLIT);
  prep<<<pgrid, 256>>>((const float*)d_in[1],
                       (const float*)d_in[8],  (const float*)d_in[9],
                       (const float*)d_in[10], (const float*)d_in[11]);
  ima_kernel<<<NB * NM * NTILE, TPB>>>(
      (const float*)d_in[0],
      (const float*)d_in[2],  (const float*)d_in[3],
      (const float*)d_in[4],  (const float*)d_in[5],
      (const float*)d_in[6],  (const float*)d_in[7],
      (float*)d_out);
}